// round 14
// baseline (speedup 1.0000x reference)
#include <cuda_runtime.h>
#include <cuda_fp16.h>
#include <math.h>
#include <stdint.h>

#define SEQ 2048
#define BATCH 2
#define DMODEL 1024
#define NHEAD 16
#define HDIM 64
#define MROWS (SEQ * BATCH)   // 4096

// Scratch (no cudaMalloc allowed) — fp16 activations/weights
__device__ __half g_q[MROWS * DMODEL];
__device__ __half g_k[MROWS * DMODEL];
__device__ __half g_v[MROWS * DMODEL];
__device__ __half g_ctx[MROWS * DMODEL];
__device__ __half g_xh[MROWS * DMODEL];
__device__ __half g_wh[4][DMODEL * DMODEL];

// ---------------- helpers ----------------
__device__ __forceinline__ void mma_f16(
    float& c0, float& c1, float& c2, float& c3,
    uint32_t a0, uint32_t a1, uint32_t a2, uint32_t a3,
    uint32_t b0, uint32_t b1)
{
    asm volatile(
        "mma.sync.aligned.m16n8k16.row.col.f32.f16.f16.f32 "
        "{%0,%1,%2,%3},{%4,%5,%6,%7},{%8,%9},{%0,%1,%2,%3};"
        : "+f"(c0), "+f"(c1), "+f"(c2), "+f"(c3)
        : "r"(a0), "r"(a1), "r"(a2), "r"(a3), "r"(b0), "r"(b1));
}

__device__ __forceinline__ void ldsm_x4(uint32_t* r, uint32_t addr) {
    asm volatile("ldmatrix.sync.aligned.m8n8.x4.shared.b16 {%0,%1,%2,%3}, [%4];"
                 : "=r"(r[0]), "=r"(r[1]), "=r"(r[2]), "=r"(r[3]) : "r"(addr));
}
__device__ __forceinline__ void ldsm_x4_trans(uint32_t* r, uint32_t addr) {
    asm volatile("ldmatrix.sync.aligned.m8n8.x4.trans.shared.b16 {%0,%1,%2,%3}, [%4];"
                 : "=r"(r[0]), "=r"(r[1]), "=r"(r[2]), "=r"(r[3]) : "r"(addr));
}

__device__ __forceinline__ float ex2(float x) {
    float r;
    asm("ex2.approx.f32 %0, %1;" : "=f"(r) : "f"(x));
    return r;
}

__device__ __forceinline__ void cpa16s(uint32_t dst, const void* src) {
    asm volatile("cp.async.cg.shared.global [%0], [%1], 16;" :: "r"(dst), "l"(src));
}
#define CP_COMMIT() asm volatile("cp.async.commit_group;")
#define CP_WAIT1()  asm volatile("cp.async.wait_group 1;")
#define CP_WAIT0()  asm volatile("cp.async.wait_group 0;")

__device__ __forceinline__ uint32_t smem_u32(const void* p) {
    return (uint32_t)__cvta_generic_to_shared(p);
}
__device__ __forceinline__ uint32_t sw64(uint32_t off)  { return off ^ ((off >> 3) & 0x30); }
__device__ __forceinline__ uint32_t sw128(uint32_t off) { return off ^ ((off >> 3) & 0x70); }

// ---------------- fused fp32 -> fp16 convert (x + 4 weights, one launch) --------
#define XBLKS (MROWS * DMODEL / 4 / 256)         // 4096
#define WBLKS (DMODEL * DMODEL / 4 / 256)        // 1024
__global__ __launch_bounds__(256) void conv_all_kernel(
    const float* __restrict__ x,
    const float* __restrict__ qw, const float* __restrict__ kw,
    const float* __restrict__ vw, const float* __restrict__ ow,
    __half* __restrict__ xh, __half* __restrict__ wh)
{
    const int bi = blockIdx.x;
    const float* src;
    __half* dst;
    int off;
    if (bi < XBLKS) {
        src = x; dst = xh; off = bi * 256;
    } else {
        const int w = (bi - XBLKS) >> 10;
        const int lb = (bi - XBLKS) & (WBLKS - 1);
        src = (w == 0) ? qw : (w == 1) ? kw : (w == 2) ? vw : ow;
        dst = wh + (size_t)w * DMODEL * DMODEL;
        off = lb * 256;
    }
    const int i = off + threadIdx.x;
    float4 v = ((const float4*)src)[i];
    __half2 h0 = __floats2half2_rn(v.x, v.y);
    __half2 h1 = __floats2half2_rn(v.z, v.w);
    ((uint2*)dst)[i] = make_uint2(*(uint32_t*)&h0, *(uint32_t*)&h1);
}

// ---------------- fp16 GEMM core (128x128 block, BK=32, 3-stage, 8 warps) -------
__device__ __forceinline__ void gemm_body(
    const __half* __restrict__ A, const __half* __restrict__ W,
    const float* __restrict__ bias, __half* Ch, float* Cf,
    int rowBase, int colBase)
{
    __shared__ __align__(1024) __half As[3][128 * 32];
    __shared__ __align__(1024) __half Bs[3][128 * 32];

    const int tid = threadIdx.x;
    const int lane = tid & 31;
    const int wid = tid >> 5;
    const int wm = wid & 3, wn = wid >> 2;
    const int g = lane >> 2, t = lane & 3;

    const uint32_t aB[3] = { smem_u32(As[0]), smem_u32(As[1]), smem_u32(As[2]) };
    const uint32_t bB[3] = { smem_u32(Bs[0]), smem_u32(Bs[1]), smem_u32(Bs[2]) };

    const int lr = lane & 7;
    const int qlo = (lane >> 3) & 1;
    const int qhi = lane >> 4;

    auto load_stage = [&](int s, int kbase) {
        #pragma unroll
        for (int i = 0; i < 2; i++) {
            const int idx = tid + i * 256;
            const int r = idx >> 2, c = idx & 3;
            const uint32_t off = sw64((uint32_t)(r * 64 + c * 16));
            cpa16s(aB[s] + off, A + (size_t)(rowBase + r) * DMODEL + kbase + c * 8);
            cpa16s(bB[s] + off, W + (size_t)(colBase + r) * DMODEL + kbase + c * 8);
        }
        CP_COMMIT();
    };

    float c[2][8][4];
    #pragma unroll
    for (int mt = 0; mt < 2; mt++)
        #pragma unroll
        for (int nt = 0; nt < 8; nt++)
            #pragma unroll
            for (int i = 0; i < 4; i++) c[mt][nt][i] = 0.0f;

    load_stage(0, 0);
    load_stage(1, 32);

    const int NIT = DMODEL / 32;   // 32
    int s = 0;
    for (int it = 0; it < NIT; it++) {
        if (it + 1 < NIT) { CP_WAIT1(); } else { CP_WAIT0(); }
        __syncthreads();
        // refill the drained buffer (== (it-1)%3) before computing
        if (it + 2 < NIT) {
            const int sn = (s + 2 >= 3) ? s - 1 : s + 2;
            load_stage(sn, (it + 2) * 32);
        }

        #pragma unroll
        for (int ks = 0; ks < 2; ks++) {
            uint32_t a[2][4], bf[4][4];
            #pragma unroll
            for (int mt = 0; mt < 2; mt++) {
                const int row = wm * 32 + mt * 16 + qlo * 8 + lr;
                const int ch = ks * 2 + qhi;
                ldsm_x4(a[mt], aB[s] + sw64((uint32_t)(row * 64 + ch * 16)));
            }
            #pragma unroll
            for (int jp = 0; jp < 4; jp++) {
                const int row = wn * 64 + (2 * jp + qhi) * 8 + lr;
                const int ch = ks * 2 + qlo;
                ldsm_x4(bf[jp], bB[s] + sw64((uint32_t)(row * 64 + ch * 16)));
            }
            #pragma unroll
            for (int mt = 0; mt < 2; mt++)
                #pragma unroll
                for (int nt = 0; nt < 8; nt++) {
                    const int jp = nt >> 1, hi = (nt & 1) * 2;
                    mma_f16(c[mt][nt][0], c[mt][nt][1], c[mt][nt][2], c[mt][nt][3],
                            a[mt][0], a[mt][1], a[mt][2], a[mt][3],
                            bf[jp][hi], bf[jp][hi + 1]);
                }
        }
        s = (s + 1 >= 3) ? 0 : s + 1;
    }

    #pragma unroll
    for (int mt = 0; mt < 2; mt++) {
        const int r0 = rowBase + wm * 32 + mt * 16 + g;
        #pragma unroll
        for (int nt = 0; nt < 8; nt++) {
            const int col = colBase + wn * 64 + nt * 8 + 2 * t;
            float2 bb = *(const float2*)&bias[col];
            float v0 = c[mt][nt][0] + bb.x, v1 = c[mt][nt][1] + bb.y;
            float v2 = c[mt][nt][2] + bb.x, v3 = c[mt][nt][3] + bb.y;
            if (Ch) {
                __half2 h0 = __floats2half2_rn(v0, v1);
                __half2 h1 = __floats2half2_rn(v2, v3);
                *(uint32_t*)&Ch[(size_t)r0 * DMODEL + col] = *(uint32_t*)&h0;
                *(uint32_t*)&Ch[(size_t)(r0 + 8) * DMODEL + col] = *(uint32_t*)&h1;
            } else {
                *(float2*)&Cf[(size_t)r0 * DMODEL + col] = make_float2(v0, v1);
                *(float2*)&Cf[(size_t)(r0 + 8) * DMODEL + col] = make_float2(v2, v3);
            }
        }
    }
}

// Fused QKV projection: blockIdx.x selects weight (0..2) and N-tile (0..7)
__global__ __launch_bounds__(256) void gemm_qkv(
    const __half* __restrict__ A, const __half* __restrict__ Wbase,
    const float* __restrict__ qb, const float* __restrict__ kb,
    const float* __restrict__ vb,
    __half* __restrict__ Oq, __half* __restrict__ Ok, __half* __restrict__ Ov)
{
    const int wsel = blockIdx.x >> 3;
    const int colBase = (blockIdx.x & 7) * 128;
    const int rowBase = blockIdx.y * 128;
    const __half* W = Wbase + (size_t)wsel * DMODEL * DMODEL;
    const float* bias = (wsel == 0) ? qb : (wsel == 1) ? kb : vb;
    __half* Ch = (wsel == 0) ? Oq : (wsel == 1) ? Ok : Ov;
    gemm_body(A, W, bias, Ch, nullptr, rowBase, colBase);
}

// Output projection (fp32 out)
__global__ __launch_bounds__(256) void gemm_out(
    const __half* __restrict__ A, const __half* __restrict__ W,
    const float* __restrict__ bias, float* __restrict__ Cf)
{
    gemm_body(A, W, bias, nullptr, Cf, blockIdx.y * 128, blockIdx.x * 128);
}

// ---------------- Flash attention (causal), fp16 mma + ldmatrix ----------------
// Scores in log2 domain. 3-stage KV ring in dynamic smem, single sync per tile.
// Dyn smem layout: Q at 0 (16KB); stage s at 16384+s*16384 (K 8KB | V 8KB).
#define ATTN_SMEM (16384 + 3 * 16384)   // 65536

__global__ __launch_bounds__(256) void attn_f16()
{
    extern __shared__ __align__(1024) char smh[];
    const uint32_t base = smem_u32(smh);
    const uint32_t qB = base;
    uint32_t kB[3], vB[3];
    #pragma unroll
    for (int s = 0; s < 3; s++) {
        kB[s] = base + 16384 + s * 16384;
        vB[s] = kB[s] + 8192;
    }

    const int tid = threadIdx.x;
    const int lane = tid & 31;
    const int wid = tid >> 5;
    const int g = lane >> 2, t = lane & 3;
    const int lr = lane & 7;
    const int qlo = (lane >> 3) & 1;
    const int qhi = lane >> 4;
    const int qt = (gridDim.x - 1) - blockIdx.x;   // heavy tiles first
    const int b = blockIdx.y & (BATCH - 1);
    const int h = blockIdx.y / BATCH;
    const int qbase = qt * 128;
    const int qr = wid * 16;

    // Stage Q scaled by log2e/8 -> scores in log2 domain
    const float qs = 0.125f * 1.4426950408889634f;
    const __half2 scl = __floats2half2_rn(qs, qs);
    #pragma unroll
    for (int i = 0; i < 4; i++) {
        const int idx = tid + i * 256;
        const int r = idx >> 3, c8 = idx & 7;
        uint4 v = *(const uint4*)(g_q + (size_t)((qbase + r) * BATCH + b) * DMODEL + h * HDIM + c8 * 8);
        __half2* hp = (__half2*)&v;
        hp[0] = __hmul2(hp[0], scl); hp[1] = __hmul2(hp[1], scl);
        hp[2] = __hmul2(hp[2], scl); hp[3] = __hmul2(hp[3], scl);
        *(uint4*)(smh + sw128((uint32_t)(r * 128 + c8 * 16))) = v;
    }

    auto load_kv = [&](int s, int t0) {
        #pragma unroll
        for (int i = 0; i < 2; i++) {
            const int idx = tid + i * 256;
            const int r = idx >> 3, c8 = idx & 7;
            const size_t go = (size_t)((t0 + r) * BATCH + b) * DMODEL + h * HDIM + c8 * 8;
            const uint32_t off = sw128((uint32_t)(r * 128 + c8 * 16));
            cpa16s(kB[s] + off, g_k + go);
            cpa16s(vB[s] + off, g_v + go);
        }
        CP_COMMIT();
    };

    const int numKT = 2 * qt + 2;
    load_kv(0, 0);
    load_kv(1, 64);

    __syncthreads();
    uint32_t qf[4][4];
    #pragma unroll
    for (int kc = 0; kc < 4; kc++) {
        const int row = qr + qlo * 8 + lr;
        const int ch = kc * 2 + qhi;
        ldsm_x4(qf[kc], qB + sw128((uint32_t)(row * 128 + ch * 16)));
    }

    float o[8][4];
    #pragma unroll
    for (int nt = 0; nt < 8; nt++)
        #pragma unroll
        for (int i = 0; i < 4; i++) o[nt][i] = 0.0f;
    float m0 = -1e30f, m1 = -1e30f, l0 = 0.0f, l1 = 0.0f;

    int s = 0;
    for (int kt = 0; kt < numKT; kt++) {
        if (kt + 1 < numKT) { CP_WAIT1(); } else { CP_WAIT0(); }
        __syncthreads();
        if (kt + 2 < numKT) {
            const int sn = (s + 2 >= 3) ? s - 1 : s + 2;
            load_kv(sn, (kt + 2) * 64);
        }

        // S = Q K^T (log2 domain)
        float sc[8][4];
        #pragma unroll
        for (int nt = 0; nt < 8; nt++) {
            sc[nt][0] = 0.f; sc[nt][1] = 0.f; sc[nt][2] = 0.f; sc[nt][3] = 0.f;
        }
        #pragma unroll
        for (int kc = 0; kc < 4; kc++) {
            uint32_t kb[4][4];
            #pragma unroll
            for (int jp = 0; jp < 4; jp++) {
                const int row = (2 * jp + qhi) * 8 + lr;
                const int ch = kc * 2 + qlo;
                ldsm_x4(kb[jp], kB[s] + sw128((uint32_t)(row * 128 + ch * 16)));
            }
            #pragma unroll
            for (int nt = 0; nt < 8; nt++) {
                const int jp = nt >> 1, hi = (nt & 1) * 2;
                mma_f16(sc[nt][0], sc[nt][1], sc[nt][2], sc[nt][3],
                        qf[kc][0], qf[kc][1], qf[kc][2], qf[kc][3],
                        kb[jp][hi], kb[jp][hi + 1]);
            }
        }

        // causal mask
        if (kt * 64 + 63 > qbase + qr) {
            const int r0 = qbase + qr + g, r1 = r0 + 8;
            #pragma unroll
            for (int nt = 0; nt < 8; nt++) {
                const int cb = kt * 64 + nt * 8 + 2 * t;
                if (cb     > r0) sc[nt][0] = -1e30f;
                if (cb + 1 > r0) sc[nt][1] = -1e30f;
                if (cb     > r1) sc[nt][2] = -1e30f;
                if (cb + 1 > r1) sc[nt][3] = -1e30f;
            }
        }

        // online softmax (log2 domain)
        float tm0 = -1e30f, tm1 = -1e30f;
        #pragma unroll
        for (int nt = 0; nt < 8; nt++) {
            tm0 = fmaxf(tm0, fmaxf(sc[nt][0], sc[nt][1]));
            tm1 = fmaxf(tm1, fmaxf(sc[nt][2], sc[nt][3]));
        }
        tm0 = fmaxf(tm0, __shfl_xor_sync(0xffffffffu, tm0, 1));
        tm0 = fmaxf(tm0, __shfl_xor_sync(0xffffffffu, tm0, 2));
        tm1 = fmaxf(tm1, __shfl_xor_sync(0xffffffffu, tm1, 1));
        tm1 = fmaxf(tm1, __shfl_xor_sync(0xffffffffu, tm1, 2));
        const float mn0 = fmaxf(m0, tm0), mn1 = fmaxf(m1, tm1);
        const float cr0 = ex2(m0 - mn0), cr1 = ex2(m1 - mn1);
        m0 = mn0; m1 = mn1;
        l0 *= cr0; l1 *= cr1;
        #pragma unroll
        for (int nt = 0; nt < 8; nt++) {
            o[nt][0] *= cr0; o[nt][1] *= cr0;
            o[nt][2] *= cr1; o[nt][3] *= cr1;
        }
        uint32_t paLo[8], paHi[8];
        float ps0 = 0.f, ps1 = 0.f;
        #pragma unroll
        for (int nt = 0; nt < 8; nt++) {
            float p0 = ex2(sc[nt][0] - mn0);
            float p1 = ex2(sc[nt][1] - mn0);
            float p2 = ex2(sc[nt][2] - mn1);
            float p3 = ex2(sc[nt][3] - mn1);
            ps0 += p0 + p1; ps1 += p2 + p3;
            __half2 h0 = __floats2half2_rn(p0, p1);
            __half2 h1 = __floats2half2_rn(p2, p3);
            paLo[nt] = *(uint32_t*)&h0;
            paHi[nt] = *(uint32_t*)&h1;
        }
        l0 += ps0; l1 += ps1;

        // O += P V
        #pragma unroll
        for (int kc = 0; kc < 4; kc++) {
            const uint32_t a0 = paLo[2 * kc];
            const uint32_t a1 = paHi[2 * kc];
            const uint32_t a2 = paLo[2 * kc + 1];
            const uint32_t a3 = paHi[2 * kc + 1];
            #pragma unroll
            for (int jp = 0; jp < 4; jp++) {
                uint32_t vb[4];
                const int row = kc * 16 + qlo * 8 + lr;
                const int ch = 2 * jp + qhi;
                ldsm_x4_trans(vb, vB[s] + sw128((uint32_t)(row * 128 + ch * 16)));
                mma_f16(o[2*jp][0], o[2*jp][1], o[2*jp][2], o[2*jp][3],
                        a0, a1, a2, a3, vb[0], vb[1]);
                mma_f16(o[2*jp+1][0], o[2*jp+1][1], o[2*jp+1][2], o[2*jp+1][3],
                        a0, a1, a2, a3, vb[2], vb[3]);
            }
        }
        s = (s + 1 >= 3) ? 0 : s + 1;
    }

    // normalize + store fp16
    l0 += __shfl_xor_sync(0xffffffffu, l0, 1);
    l0 += __shfl_xor_sync(0xffffffffu, l0, 2);
    l1 += __shfl_xor_sync(0xffffffffu, l1, 1);
    l1 += __shfl_xor_sync(0xffffffffu, l1, 2);
    const float inv0 = 1.0f / l0, inv1 = 1.0f / l1;
    const int r0 = qbase + qr + g;
    #pragma unroll
    for (int nt = 0; nt < 8; nt++) {
        const int col = h * HDIM + nt * 8 + 2 * t;
        __half2 h0 = __floats2half2_rn(o[nt][0] * inv0, o[nt][1] * inv0);
        __half2 h1 = __floats2half2_rn(o[nt][2] * inv1, o[nt][3] * inv1);
        *(uint32_t*)&g_ctx[(size_t)(r0 * BATCH + b) * DMODEL + col] = *(uint32_t*)&h0;
        *(uint32_t*)&g_ctx[(size_t)((r0 + 8) * BATCH + b) * DMODEL + col] = *(uint32_t*)&h1;
    }
}

// ---------------- launch ----------------
extern "C" void kernel_launch(void* const* d_in, const int* in_sizes, int n_in,
                              void* d_out, int out_size)
{
    const float* x  = (const float*)d_in[0];
    const float* qw = (const float*)d_in[1];
    const float* qb = (const float*)d_in[2];
    const float* kw = (const float*)d_in[3];
    const float* kb = (const float*)d_in[4];
    const float* vw = (const float*)d_in[5];
    const float* vb = (const float*)d_in[6];
    const float* ow = (const float*)d_in[7];
    const float* ob = (const float*)d_in[8];
    // d_in[9] = attn_mask: causal, applied analytically.
    float* out = (float*)d_out;

    void *pq, *pk, *pv, *pc, *pxh, *pwh;
    cudaGetSymbolAddress(&pq, g_q);
    cudaGetSymbolAddress(&pk, g_k);
    cudaGetSymbolAddress(&pv, g_v);
    cudaGetSymbolAddress(&pc, g_ctx);
    cudaGetSymbolAddress(&pxh, g_xh);
    cudaGetSymbolAddress(&pwh, g_wh);
    __half* xh = (__half*)pxh;
    __half* wh = (__half*)pwh;
    __half* w3 = wh + (size_t)3 * DMODEL * DMODEL;

    cudaFuncSetAttribute(attn_f16, cudaFuncAttributeMaxDynamicSharedMemorySize, ATTN_SMEM);

    conv_all_kernel<<<XBLKS + 4 * WBLKS, 256>>>(x, qw, kw, vw, ow, xh, wh);

    gemm_qkv<<<dim3(24, MROWS / 128), 256>>>(xh, wh, qb, kb, vb,
                                             (__half*)pq, (__half*)pk, (__half*)pv);
    attn_f16<<<dim3(SEQ / 128, BATCH * NHEAD), 256, ATTN_SMEM>>>();
    gemm_out<<<dim3(DMODEL / 128, MROWS / 128), 256>>>((const __half*)pc, w3, ob, out);
}